// round 3
// baseline (speedup 1.0000x reference)
#include <cuda_runtime.h>
#include <cuda_bf16.h>
#include <cstdint>

// ============================================================================
// Problem constants
// ============================================================================
static constexpr int Bb    = 2;
static constexpr int Ss    = 2048;
static constexpr int Dd    = 2048;
static constexpr int Vv    = 50257;
static constexpr int SEQ   = Ss - 1;             // 2047 shifted length
static constexpr int NROWS = Bb * SEQ;           // 4094 valid rows
static constexpr int MPAD  = 4096;               // padded rows
static constexpr int MT    = MPAD / 128;         // 32 M-tiles
static constexpr int BN    = 128;                // vocab cols per CTA
static constexpr int VT    = (Vv + BN - 1) / BN; // 393 V-tiles
static constexpr int VPAD  = VT * BN;            // 50304
static constexpr int K     = 2048;
static constexpr int KSLAB = 64;                 // bf16 per K slab (128 B rows)
static constexpr int NSLAB = K / KSLAB;          // 32

// SMEM: stage s at s*32768 { A 16KB, B 16KB }, bias at 65536 (512B)
static constexpr int SMEM_STAGE = 32768;
static constexpr int SMEM_BIAS  = 65536;
static constexpr int SMEM_TOTAL = SMEM_BIAS + 512;

// ============================================================================
// Device scratch (__device__ globals: allocation-free rule)
// ============================================================================
__device__ __align__(256) __nv_bfloat16 g_Ebf[(size_t)MPAD * K];   // 16.8 MB
__device__ __align__(256) __nv_bfloat16 g_Wbf[(size_t)VPAD * K];   // 206 MB
__device__ __align__(256) float         g_biasPad[VPAD];
__device__ float g_Pm[(size_t)VT * MPAD];
__device__ float g_Ps[(size_t)VT * MPAD];
__device__ float g_tl[MPAD];
__device__ int   g_valid[MPAD];
__device__ float g_row_nll[MPAD];
__device__ int   g_label64;

// ============================================================================
// Helpers
// ============================================================================
__device__ __forceinline__ uint32_t smem_u32(const void* p) {
    uint32_t a;
    asm("{ .reg .u64 t; cvta.to.shared.u64 t, %1; cvt.u32.u64 %0, t; }" : "=r"(a) : "l"(p));
    return a;
}
__device__ __forceinline__ void cp16(uint32_t dst, const void* src) {
    asm volatile("cp.async.cg.shared.global [%0], [%1], 16;" :: "r"(dst), "l"(src));
}
__device__ __forceinline__ void cp_commit() {
    asm volatile("cp.async.commit_group;" ::: "memory");
}
template <int N>
__device__ __forceinline__ void cp_wait() {
    asm volatile("cp.async.wait_group %0;" :: "n"(N) : "memory");
}
__device__ __forceinline__ void ldm_x4(uint32_t* r, uint32_t addr) {
    asm volatile("ldmatrix.sync.aligned.m8n8.x4.shared.b16 {%0,%1,%2,%3}, [%4];"
                 : "=r"(r[0]), "=r"(r[1]), "=r"(r[2]), "=r"(r[3]) : "r"(addr));
}
__device__ __forceinline__ void mma16816(float* c, const uint32_t* a,
                                         uint32_t b0, uint32_t b1) {
    asm volatile(
        "mma.sync.aligned.m16n8k16.row.col.f32.bf16.bf16.f32 "
        "{%0,%1,%2,%3}, {%4,%5,%6,%7}, {%8,%9}, {%0,%1,%2,%3};"
        : "+f"(c[0]), "+f"(c[1]), "+f"(c[2]), "+f"(c[3])
        : "r"(a[0]), "r"(a[1]), "r"(a[2]), "r"(a[3]), "r"(b0), "r"(b1));
}
__device__ __forceinline__ void lse_merge(float& M, float& S, float m2, float s2) {
    float nm = fmaxf(M, m2);
    S = S * __expf(M - nm) + s2 * __expf(m2 - nm);
    M = nm;
}

// ============================================================================
// Kernel 0: label dtype sniff (int64 vs int32)
// ============================================================================
__global__ void detect_kernel(const unsigned* labels) {
    __shared__ int any;
    if (threadIdx.x == 0) any = 0;
    __syncthreads();
    int loc = 0;
    for (int i = threadIdx.x; i < (Bb * Ss) / 2; i += 256)
        if (labels[2 * i + 1] != 0u) loc = 1;
    if (loc) atomicOr(&any, 1);
    __syncthreads();
    if (threadIdx.x == 0) g_label64 = !any;    // all odd words zero => int64
}

// ============================================================================
// Kernel 1: shifted embeddings -> bf16, zero-pad rows to MPAD
// ============================================================================
__global__ void conv_e_kernel(const float* __restrict__ emb) {
    int i = blockIdx.x * 256 + threadIdx.x;    // bf16-pair index
    if (i >= MPAD * (K / 2)) return;
    int row = i / (K / 2), p = i % (K / 2);
    float x = 0.f, y = 0.f;
    if (row < NROWS) {
        int b = row / SEQ, s = row % SEQ;
        const float2 v = *(const float2*)(emb + ((size_t)(b * Ss + s)) * Dd + 2 * p);
        x = v.x; y = v.y;
    }
    ((__nv_bfloat162*)g_Ebf)[i] = __floats2bfloat162_rn(x, y);
}

// ============================================================================
// Kernel 2: weight -> bf16, zero-pad vocab rows to VPAD
// ============================================================================
__global__ void conv_w_kernel(const float* __restrict__ w) {
    size_t i = (size_t)blockIdx.x * 256 + threadIdx.x;
    if (i >= (size_t)VPAD * (K / 2)) return;
    int row = (int)(i / (K / 2)), p = (int)(i % (K / 2));
    float x = 0.f, y = 0.f;
    if (row < Vv) {
        const float2 v = *(const float2*)(w + (size_t)row * Dd + 2 * p);
        x = v.x; y = v.y;
    }
    ((__nv_bfloat162*)g_Wbf)[i] = __floats2bfloat162_rn(x, y);
}

// ============================================================================
// Kernel 3: pad bias (-inf on pad cols => exp contributes 0)
// ============================================================================
__global__ void conv_bias_kernel(const float* __restrict__ bias) {
    int i = blockIdx.x * 256 + threadIdx.x;
    if (i >= VPAD) return;
    g_biasPad[i] = (i < Vv) ? bias[i] : __int_as_float(0xff800000);
}

// ============================================================================
// Kernel 4: bf16 HMMA GEMM (128x128 tile) + fused online-LSE partials
// Grid (MT, VT), 256 threads = 8 warps (warp_m = wid&3, warp_n = wid>>2).
// Warp tile 32x64: 2 m16-tiles x 8 n8-tiles, m16n8k16 accumulation.
// ============================================================================
__global__ void __launch_bounds__(256) gemm_lse_kernel() {
    extern __shared__ char smem[];
    const uint32_t sb = smem_u32(smem);
    float* bias_s = (float*)(smem + SMEM_BIAS);

    const int tid = threadIdx.x, wid = tid >> 5, lid = tid & 31;
    const int warp_m = wid & 3, warp_n = wid >> 2;
    const int m0 = blockIdx.x * 128;
    const int n0 = blockIdx.y * BN;

    const __nv_bfloat16* Abase = g_Ebf + (size_t)m0 * K;
    const __nv_bfloat16* Bbase = g_Wbf + (size_t)n0 * K;

    // bias tile -> smem
    if (tid < 128) bias_s[tid] = g_biasPad[n0 + tid];

    // per-thread load coords: 4 chunks of A and B per slab
    const int lr = tid >> 3;            // base row (0..31), +32*j
    const int lc = tid & 7;             // 16B chunk in row

    // ---- prefetch slab 0 ----
    {
        const __nv_bfloat16* A = Abase;      // slab 0
        const __nv_bfloat16* Bp = Bbase;
        uint32_t sA = sb, sB = sb + 16384;
        #pragma unroll
        for (int j = 0; j < 4; ++j) {
            int r = lr + 32 * j;
            uint32_t so = r * 128 + ((lc ^ (r & 7)) << 4);
            cp16(sA + so, A + (size_t)r * K + lc * 8);
            cp16(sB + so, Bp + (size_t)r * K + lc * 8);
        }
        cp_commit();
    }

    float acc[2][8][4];
    #pragma unroll
    for (int mt = 0; mt < 2; ++mt)
        #pragma unroll
        for (int nt = 0; nt < 8; ++nt)
            #pragma unroll
            for (int q = 0; q < 4; ++q) acc[mt][nt][q] = 0.f;

    for (int s = 0; s < NSLAB; ++s) {
        if (s + 1 < NSLAB) {
            const __nv_bfloat16* A = Abase + (s + 1) * KSLAB;
            const __nv_bfloat16* Bp = Bbase + (s + 1) * KSLAB;
            uint32_t sA = sb + ((s + 1) & 1) * SMEM_STAGE, sB = sA + 16384;
            #pragma unroll
            for (int j = 0; j < 4; ++j) {
                int r = lr + 32 * j;
                uint32_t so = r * 128 + ((lc ^ (r & 7)) << 4);
                cp16(sA + so, A + (size_t)r * K + lc * 8);
                cp16(sB + so, Bp + (size_t)r * K + lc * 8);
            }
            cp_commit();
            cp_wait<1>();
        } else {
            cp_wait<0>();
        }
        __syncthreads();

        const uint32_t sA = sb + (s & 1) * SMEM_STAGE, sB = sA + 16384;
        #pragma unroll
        for (int ks = 0; ks < 4; ++ks) {
            uint32_t afr[2][4];
            #pragma unroll
            for (int mt = 0; mt < 2; ++mt) {
                int m = warp_m * 32 + mt * 16 + (lid & 15);
                int c = ks * 2 + (lid >> 4);
                ldm_x4(afr[mt], sA + m * 128 + ((c ^ (m & 7)) << 4));
            }
            uint32_t bfr[4][4];
            #pragma unroll
            for (int nt2 = 0; nt2 < 4; ++nt2) {
                int n = warp_n * 64 + nt2 * 16 + (lid & 7) + ((lid >> 4) << 3);
                int c = ks * 2 + ((lid >> 3) & 1);
                ldm_x4(bfr[nt2], sB + n * 128 + ((c ^ (n & 7)) << 4));
            }
            #pragma unroll
            for (int mt = 0; mt < 2; ++mt)
                #pragma unroll
                for (int nt = 0; nt < 8; ++nt)
                    mma16816(acc[mt][nt], afr[mt],
                             bfr[nt >> 1][(nt & 1) * 2], bfr[nt >> 1][(nt & 1) * 2 + 1]);
        }
        __syncthreads();
    }

    // ---- fused epilogue: per-row online (max, sum-exp) over the 128-col tile
    float2* stage = (float2*)smem;      // stage[warp_n][row] : 2 x 128 float2 (aliases dead bufs)

    #pragma unroll
    for (int mt = 0; mt < 2; ++mt) {
        #pragma unroll
        for (int h = 0; h < 2; ++h) {
            const int row = warp_m * 32 + mt * 16 + h * 8 + (lid >> 2);
            float rm = __int_as_float(0xff800000);
            #pragma unroll
            for (int nt = 0; nt < 8; ++nt) {
                int col = warp_n * 64 + nt * 8 + (lid & 3) * 2;
                rm = fmaxf(rm, fmaxf(acc[mt][nt][h * 2 + 0] + bias_s[col],
                                     acc[mt][nt][h * 2 + 1] + bias_s[col + 1]));
            }
            float rs = 0.f;
            #pragma unroll
            for (int nt = 0; nt < 8; ++nt) {
                int col = warp_n * 64 + nt * 8 + (lid & 3) * 2;
                rs += __expf(acc[mt][nt][h * 2 + 0] + bias_s[col] - rm);
                rs += __expf(acc[mt][nt][h * 2 + 1] + bias_s[col + 1] - rm);
            }
            // merge across the 4 lanes of the quad (same row)
            #pragma unroll
            for (int off = 1; off <= 2; off <<= 1) {
                float om = __shfl_xor_sync(0xffffffff, rm, off);
                float os = __shfl_xor_sync(0xffffffff, rs, off);
                lse_merge(rm, rs, om, os);
            }
            if ((lid & 3) == 0) stage[warp_n * 128 + row] = make_float2(rm, rs);
        }
    }
    __syncthreads();

    if (tid < 128) {
        float2 p0 = stage[tid], p1 = stage[128 + tid];
        float M = p0.x, S = p0.y;
        lse_merge(M, S, p1.x, p1.y);
        const size_t o = (size_t)blockIdx.y * MPAD + m0 + tid;
        g_Pm[o] = M;
        g_Ps[o] = S;
    }
}

// ============================================================================
// Kernel 5: exact fp32 true logits (one block per valid row)
// ============================================================================
__global__ void tl_kernel(const float* __restrict__ emb, const float* __restrict__ w,
                          const float* __restrict__ bias, const void* __restrict__ labels) {
    const int r = blockIdx.x;
    const int b = r / SEQ, s = r % SEQ;
    long long y;
    if (g_label64) y = ((const long long*)labels)[(size_t)b * Ss + s + 1];
    else           y = (long long)((const int*)labels)[b * Ss + s + 1];
    const bool valid = (y >= 0) && (y < Vv);
    const int yy = valid ? (int)y : 0;

    const float4* er = (const float4*)(emb + ((size_t)(b * Ss + s)) * Dd);
    const float4* wr = (const float4*)(w + (size_t)yy * Dd);
    float acc = 0.f;
    for (int i = threadIdx.x; i < Dd / 4; i += 256) {
        float4 a = er[i], q = wr[i];
        acc += a.x * q.x + a.y * q.y + a.z * q.z + a.w * q.w;
    }
    __shared__ float red[256];
    red[threadIdx.x] = acc;
    __syncthreads();
    for (int o = 128; o > 0; o >>= 1) {
        if (threadIdx.x < o) red[threadIdx.x] += red[threadIdx.x + o];
        __syncthreads();
    }
    if (threadIdx.x == 0) {
        g_tl[r] = red[0] + bias[yy];
        g_valid[r] = valid ? 1 : 0;
    }
}

// ============================================================================
// Kernel 6: per-row merge of VT partials -> nll
// ============================================================================
__global__ void rowlse_kernel() {
    int r = blockIdx.x * 256 + threadIdx.x;
    if (r >= MPAD) return;
    float nll = 0.f;
    if (r < NROWS) {
        float M = __int_as_float(0xff800000), S = 0.f;
        for (int vt = 0; vt < VT; ++vt)
            lse_merge(M, S, g_Pm[(size_t)vt * MPAD + r], g_Ps[(size_t)vt * MPAD + r]);
        float lse = M + logf(S);
        nll = g_valid[r] ? (lse - g_tl[r]) : 0.f;
    }
    g_row_nll[r] = nll;
}

// ============================================================================
// Kernel 7: deterministic final reduction -> scalar loss
// ============================================================================
__global__ void final_kernel(float* __restrict__ out) {
    __shared__ float red[256];
    __shared__ int cred[256];
    float a = 0.f; int c = 0;
    for (int i = threadIdx.x; i < MPAD; i += 256) {
        a += g_row_nll[i];
        if (i < NROWS) c += g_valid[i];
    }
    red[threadIdx.x] = a; cred[threadIdx.x] = c;
    __syncthreads();
    for (int o = 128; o > 0; o >>= 1) {
        if (threadIdx.x < o) {
            red[threadIdx.x] += red[threadIdx.x + o];
            cred[threadIdx.x] += cred[threadIdx.x + o];
        }
        __syncthreads();
    }
    if (threadIdx.x == 0) out[0] = red[0] / (float)max(cred[0], 1);
}

// ============================================================================
// kernel_launch — graph-capturable, allocation-free
// ============================================================================
extern "C" void kernel_launch(void* const* d_in, const int* in_sizes, int n_in,
                              void* d_out, int out_size) {
    const float* emb    = (const float*)d_in[0];
    const float* w      = (const float*)d_in[1];
    const float* bias   = (const float*)d_in[2];
    const void*  labels = d_in[3];

    cudaFuncSetAttribute(gemm_lse_kernel, cudaFuncAttributeMaxDynamicSharedMemorySize,
                         SMEM_TOTAL);

    detect_kernel<<<1, 256>>>((const unsigned*)labels);
    conv_e_kernel<<<(MPAD * (K / 2) + 255) / 256, 256>>>(emb);
    {
        size_t n = (size_t)VPAD * (K / 2);
        conv_w_kernel<<<(unsigned)((n + 255) / 256), 256>>>(w);
    }
    conv_bias_kernel<<<(VPAD + 255) / 256, 256>>>(bias);

    dim3 grid(MT, VT);
    gemm_lse_kernel<<<grid, 256, SMEM_TOTAL>>>();

    tl_kernel<<<NROWS, 256>>>(emb, w, bias, labels);
    rowlse_kernel<<<MPAD / 256, 256>>>();
    final_kernel<<<1, 256>>>((float*)d_out);
}